// round 10
// baseline (speedup 1.0000x reference)
#include <cuda_runtime.h>
#include <cstddef>
#include <cstdint>

#define Bb   4
#define Ss   2048
#define DIN  512
#define Hh   8
#define DM   512
#define MROWS (Bb*Ss)          // 8192

// Scratch (device globals: allocation-free rule)
__device__ float g_Q [MROWS*DM];
__device__ float g_K [MROWS*DM];
__device__ float g_V [MROWS*DM];
__device__ float g_AO[MROWS*DM];
__device__ float g_P [MROWS*DIN];

// ===========================================================================
// helpers
// ===========================================================================
__device__ __forceinline__ uint32_t f2tf32(float f) {
    uint32_t r;
    asm("cvt.rna.tf32.f32 %0, %1;" : "=r"(r) : "f"(f));
    return r;
}

// D += A * B  (m16n8k8, tf32 inputs, fp32 accum). row.col.
__device__ __forceinline__ void mma_tf32(float* d, const uint32_t* a,
                                         uint32_t b0, uint32_t b1) {
    asm volatile(
        "mma.sync.aligned.m16n8k8.row.col.f32.tf32.tf32.f32 "
        "{%0,%1,%2,%3}, {%4,%5,%6,%7}, {%8,%9}, {%0,%1,%2,%3};"
        : "+f"(d[0]), "+f"(d[1]), "+f"(d[2]), "+f"(d[3])
        : "r"(a[0]), "r"(a[1]), "r"(a[2]), "r"(a[3]), "r"(b0), "r"(b1));
}

__device__ __forceinline__ void ldsm_x4(uint32_t* r, uint32_t addr) {
    asm volatile("ldmatrix.sync.aligned.m8n8.x4.shared.b16 {%0,%1,%2,%3}, [%4];"
                 : "=r"(r[0]), "=r"(r[1]), "=r"(r[2]), "=r"(r[3]) : "r"(addr));
}

// ===========================================================================
// Tensor-core GEMM, software-pipelined: next k-tile staged in regs during MMA.
// BM=128, BN=128, BK=32, 256 threads, 2 CTAs/SM.
// X staging: 4 float4/thread (rows tid>>1, col base (tid&1)*16) = full tile.
// ===========================================================================
#define XS_STR 36
#define WS_STR 136

__global__ __launch_bounds__(256, 2)
void gemm_tc_kernel(const float* __restrict__ X, const float* __restrict__ W,
                    const float* __restrict__ bias, float* __restrict__ C) {
    __shared__ float Xs[128 * XS_STR];
    __shared__ float Ws[32 * WS_STR];

    const int tid  = threadIdx.x;
    const int lane = tid & 31;
    const int wid  = tid >> 5;
    const int gid  = lane >> 2;
    const int tig  = lane & 3;

    const int warp_m = wid >> 2;
    const int warp_n = wid & 3;
    const int m_base = warp_m * 64;
    const int n_base = warp_n * 32;

    const int bm = blockIdx.x * 128;
    const int bn = blockIdx.y * 128;

    // per-thread load coordinates (full-tile coverage)
    const int xr0 = tid >> 1;                 // X row 0..127
    const int xc0 = (tid & 1) * 16;           // X col base: 0 or 16 (4 float4)
    const int wr0 = tid >> 3;                 // W row 0..31
    const int wc0 = (tid & 7) * 16;           // W col base (4 float4)

    float4 xs0, xs1, xs2, xs3, ws0, ws1, ws2, ws3;

    auto ldg_tile = [&](int k0) {
        const float* xp = X + (size_t)(bm + xr0) * 512 + k0 + xc0;
        xs0 = *(const float4*)(xp);
        xs1 = *(const float4*)(xp + 4);
        xs2 = *(const float4*)(xp + 8);
        xs3 = *(const float4*)(xp + 12);
        const float* wp = W + (size_t)(k0 + wr0) * 512 + bn + wc0;
        ws0 = *(const float4*)(wp);
        ws1 = *(const float4*)(wp + 4);
        ws2 = *(const float4*)(wp + 8);
        ws3 = *(const float4*)(wp + 12);
    };
    auto sts_tile = [&]() {
        uint4 t0 = { f2tf32(xs0.x), f2tf32(xs0.y), f2tf32(xs0.z), f2tf32(xs0.w) };
        uint4 t1 = { f2tf32(xs1.x), f2tf32(xs1.y), f2tf32(xs1.z), f2tf32(xs1.w) };
        uint4 t2 = { f2tf32(xs2.x), f2tf32(xs2.y), f2tf32(xs2.z), f2tf32(xs2.w) };
        uint4 t3 = { f2tf32(xs3.x), f2tf32(xs3.y), f2tf32(xs3.z), f2tf32(xs3.w) };
        *(uint4*)(Xs + xr0 * XS_STR + xc0)      = t0;
        *(uint4*)(Xs + xr0 * XS_STR + xc0 + 4)  = t1;
        *(uint4*)(Xs + xr0 * XS_STR + xc0 + 8)  = t2;
        *(uint4*)(Xs + xr0 * XS_STR + xc0 + 12) = t3;
        uint4 u0 = { f2tf32(ws0.x), f2tf32(ws0.y), f2tf32(ws0.z), f2tf32(ws0.w) };
        uint4 u1 = { f2tf32(ws1.x), f2tf32(ws1.y), f2tf32(ws1.z), f2tf32(ws1.w) };
        uint4 u2 = { f2tf32(ws2.x), f2tf32(ws2.y), f2tf32(ws2.z), f2tf32(ws2.w) };
        uint4 u3 = { f2tf32(ws3.x), f2tf32(ws3.y), f2tf32(ws3.z), f2tf32(ws3.w) };
        *(uint4*)(Ws + wr0 * WS_STR + wc0)      = u0;
        *(uint4*)(Ws + wr0 * WS_STR + wc0 + 4)  = u1;
        *(uint4*)(Ws + wr0 * WS_STR + wc0 + 8)  = u2;
        *(uint4*)(Ws + wr0 * WS_STR + wc0 + 12) = u3;
    };

    float acc[4][4][4];
    #pragma unroll
    for (int mf = 0; mf < 4; mf++)
        #pragma unroll
        for (int nf = 0; nf < 4; nf++)
            #pragma unroll
            for (int c = 0; c < 4; c++) acc[mf][nf][c] = 0.f;

    ldg_tile(0);
    sts_tile();
    __syncthreads();

    for (int k0 = 0; k0 < 512; k0 += 32) {
        // prefetch next tile into regs; latency hidden by MMA phase below
        if (k0 < 480) ldg_tile(k0 + 32);

        #pragma unroll
        for (int ks = 0; ks < 4; ks++) {
            const int kk = ks * 8;
            uint32_t A[4][4];
            #pragma unroll
            for (int mf = 0; mf < 4; mf++) {
                const float* ap = Xs + (m_base + mf * 16 + gid) * XS_STR + kk + tig;
                A[mf][0] = __float_as_uint(ap[0]);
                A[mf][1] = __float_as_uint(ap[8 * XS_STR]);
                A[mf][2] = __float_as_uint(ap[4]);
                A[mf][3] = __float_as_uint(ap[8 * XS_STR + 4]);
            }
            #pragma unroll
            for (int nf = 0; nf < 4; nf++) {
                const float* bp = Ws + (kk + tig) * WS_STR + n_base + nf * 8 + gid;
                uint32_t b0 = __float_as_uint(bp[0]);
                uint32_t b1 = __float_as_uint(bp[4 * WS_STR]);
                #pragma unroll
                for (int mf = 0; mf < 4; mf++)
                    mma_tf32(acc[mf][nf], A[mf], b0, b1);
            }
        }
        __syncthreads();
        if (k0 < 480) {
            sts_tile();
            __syncthreads();
        }
    }

    #pragma unroll
    for (int nf = 0; nf < 4; nf++) {
        const int col = bn + n_base + nf * 8 + 2 * tig;
        float2 b2 = *(const float2*)(bias + col);
        #pragma unroll
        for (int mf = 0; mf < 4; mf++) {
            const int row0 = bm + m_base + mf * 16 + gid;
            float2 o0 = { acc[mf][nf][0] + b2.x, acc[mf][nf][1] + b2.y };
            float2 o1 = { acc[mf][nf][2] + b2.x, acc[mf][nf][3] + b2.y };
            *(float2*)(C + (size_t)row0 * 512 + col) = o0;
            *(float2*)(C + (size_t)(row0 + 8) * 512 + col) = o1;
        }
    }
}

// ===========================================================================
// mma.sync tf32 flash attention, v4 (proven R8 version, unchanged).
// ===========================================================================
#define KSTR 68
#define VSTR 72
#define SM_K0 0
#define SM_K1 (32*KSTR)
#define SM_V0 (2*32*KSTR)
#define SM_V1 (SM_V0 + 32*VSTR)
#define ATTN_SMEM_FLOATS (SM_V0 + 2*32*VSTR)   // 8960 floats = 35840 B

__global__ __launch_bounds__(128, 2)
void attn_mma_kernel(const float* __restrict__ Qg, const float* __restrict__ Kg,
                     const float* __restrict__ Vg, const float* __restrict__ mask,
                     float* __restrict__ AO) {
    __shared__ float sm[ATTN_SMEM_FLOATS];
    const int tid  = threadIdx.x;
    const int lane = tid & 31;
    const int wid  = tid >> 5;        // 0..3
    const int gid  = lane >> 2;
    const int tig  = lane & 3;
    const int srcA = (lane & ~3) | (tig >> 1);
    const int srcB = srcA + 2;
    const bool odd = (tig & 1);

    const int lm_base = (lane & 7) * KSTR + ((lane >> 3) & 1) * 4 + (lane >> 4) * 8;
    const uint32_t smK0_u = (uint32_t)__cvta_generic_to_shared(sm + SM_K0);
    const uint32_t smK1_u = (uint32_t)__cvta_generic_to_shared(sm + SM_K1);

    const int bh = blockIdx.y;
    const int b  = bh >> 3;
    const int h  = bh & 7;
    const int q0 = blockIdx.x * 128;

    const float* Kb = Kg + (size_t)b * Ss * 512 + h * 64;
    const float* Vb = Vg + (size_t)b * Ss * 512 + h * 64;

    const int qrow0 = q0 + wid * 32 + gid;
    const int qrow1 = qrow0 + 16;
    uint32_t Qa[2][8][4];
    #pragma unroll
    for (int mf = 0; mf < 2; mf++) {
        const float* Qp = Qg + ((size_t)b * Ss + (mf ? qrow1 : qrow0)) * 512 + h * 64;
        #pragma unroll
        for (int ch = 0; ch < 8; ch++) {
            Qa[mf][ch][0] = f2tf32(Qp[ch * 8 + tig] * 0.125f);
            Qa[mf][ch][1] = f2tf32(Qp[8 * 512 + ch * 8 + tig] * 0.125f);
            Qa[mf][ch][2] = f2tf32(Qp[ch * 8 + tig + 4] * 0.125f);
            Qa[mf][ch][3] = f2tf32(Qp[8 * 512 + ch * 8 + tig + 4] * 0.125f);
        }
    }

    auto load_kv = [&](int k0, int sel) {
        float* Ks = sm + (sel ? SM_K1 : SM_K0);
        float* Vs = sm + (sel ? SM_V1 : SM_V0);
        #pragma unroll
        for (int l = 0; l < 4; l++) {
            int e = tid + l * 128;
            int r = e >> 4, c4 = e & 15;
            float4 kv = *(const float4*)(Kb + (size_t)(k0 + r) * 512 + c4 * 4);
            uint4 tk = { f2tf32(kv.x), f2tf32(kv.y), f2tf32(kv.z), f2tf32(kv.w) };
            *(uint4*)(Ks + r * KSTR + c4 * 4) = tk;
            float4 vv = *(const float4*)(Vb + (size_t)(k0 + r) * 512 + c4 * 4);
            uint4 tv = { f2tf32(vv.x), f2tf32(vv.y), f2tf32(vv.z), f2tf32(vv.w) };
            *(uint4*)(Vs + r * VSTR + c4 * 4) = tv;
        }
    };

    load_kv(0, 0);

    const float* Mr[4];
    Mr[0] = mask + (size_t)b * Ss * Ss + (size_t)qrow0 * Ss;
    Mr[1] = Mr[0] + (size_t)8 * Ss;
    Mr[2] = mask + (size_t)b * Ss * Ss + (size_t)qrow1 * Ss;
    Mr[3] = Mr[2] + (size_t)8 * Ss;

    float mI[4] = {-1e30f, -1e30f, -1e30f, -1e30f};
    float lI[4] = {0.f, 0.f, 0.f, 0.f};
    float O[2][8][4];
    #pragma unroll
    for (int mf = 0; mf < 2; mf++)
        #pragma unroll
        for (int j = 0; j < 8; j++)
            #pragma unroll
            for (int c = 0; c < 4; c++) O[mf][j][c] = 0.f;

    __syncthreads();

    for (int kt = 0; kt < 64; kt++) {
        const int sel = kt & 1;
        const int k0  = kt * 32;
        const float* Vs = sm + (sel ? SM_V1 : SM_V0);
        const uint32_t smK_u = sel ? smK1_u : smK0_u;

        float2 mk[4][4];
        #pragma unroll
        for (int r = 0; r < 4; r++)
            #pragma unroll
            for (int kf = 0; kf < 4; kf++)
                mk[r][kf] = *(const float2*)(Mr[r] + k0 + kf * 8 + 2 * tig);

        float S[2][4][4];
        #pragma unroll
        for (int mf = 0; mf < 2; mf++)
            #pragma unroll
            for (int kf = 0; kf < 4; kf++)
                #pragma unroll
                for (int c = 0; c < 4; c++) S[mf][kf][c] = 0.f;

        #pragma unroll
        for (int kf = 0; kf < 4; kf++) {
            #pragma unroll
            for (int ch2 = 0; ch2 < 4; ch2++) {
                uint32_t r[4];
                ldsm_x4(r, smK_u + 4u * (uint32_t)(kf * 8 * KSTR + ch2 * 16 + lm_base));
                mma_tf32(S[0][kf], Qa[0][2 * ch2],     r[0], r[1]);
                mma_tf32(S[0][kf], Qa[0][2 * ch2 + 1], r[2], r[3]);
                mma_tf32(S[1][kf], Qa[1][2 * ch2],     r[0], r[1]);
                mma_tf32(S[1][kf], Qa[1][2 * ch2 + 1], r[2], r[3]);
            }
        }

        if (kt < 63) load_kv(k0 + 32, sel ^ 1);

        #pragma unroll
        for (int mf = 0; mf < 2; mf++) {
            const int rA = mf * 2, rB = mf * 2 + 1;
            float mx0 = mI[rA], mx1 = mI[rB];
            #pragma unroll
            for (int kf = 0; kf < 4; kf++) {
                float s0 = S[mf][kf][0] * mk[rA][kf].x;
                float s1 = S[mf][kf][1] * mk[rA][kf].y;
                float s2 = S[mf][kf][2] * mk[rB][kf].x;
                float s3 = S[mf][kf][3] * mk[rB][kf].y;
                s0 = (s0 > 0.f) ? s0 : -10000.f;
                s1 = (s1 > 0.f) ? s1 : -10000.f;
                s2 = (s2 > 0.f) ? s2 : -10000.f;
                s3 = (s3 > 0.f) ? s3 : -10000.f;
                S[mf][kf][0] = s0; S[mf][kf][1] = s1;
                S[mf][kf][2] = s2; S[mf][kf][3] = s3;
                mx0 = fmaxf(mx0, fmaxf(s0, s1));
                mx1 = fmaxf(mx1, fmaxf(s2, s3));
            }
            mx0 = fmaxf(mx0, __shfl_xor_sync(0xffffffffu, mx0, 1));
            mx0 = fmaxf(mx0, __shfl_xor_sync(0xffffffffu, mx0, 2));
            mx1 = fmaxf(mx1, __shfl_xor_sync(0xffffffffu, mx1, 1));
            mx1 = fmaxf(mx1, __shfl_xor_sync(0xffffffffu, mx1, 2));

            float f0 = __expf(mI[rA] - mx0);
            float f1 = __expf(mI[rB] - mx1);
            float sum0 = 0.f, sum1 = 0.f;
            #pragma unroll
            for (int kf = 0; kf < 4; kf++) {
                float p0 = __expf(S[mf][kf][0] - mx0);
                float p1 = __expf(S[mf][kf][1] - mx0);
                float p2 = __expf(S[mf][kf][2] - mx1);
                float p3 = __expf(S[mf][kf][3] - mx1);
                sum0 += p0 + p1;
                sum1 += p2 + p3;
                S[mf][kf][0] = __uint_as_float(f2tf32(p0));
                S[mf][kf][1] = __uint_as_float(f2tf32(p1));
                S[mf][kf][2] = __uint_as_float(f2tf32(p2));
                S[mf][kf][3] = __uint_as_float(f2tf32(p3));
            }
            sum0 += __shfl_xor_sync(0xffffffffu, sum0, 1);
            sum0 += __shfl_xor_sync(0xffffffffu, sum0, 2);
            sum1 += __shfl_xor_sync(0xffffffffu, sum1, 1);
            sum1 += __shfl_xor_sync(0xffffffffu, sum1, 2);

            lI[rA] = lI[rA] * f0 + sum0;  mI[rA] = mx0;
            lI[rB] = lI[rB] * f1 + sum1;  mI[rB] = mx1;

            #pragma unroll
            for (int j = 0; j < 8; j++) {
                O[mf][j][0] *= f0; O[mf][j][1] *= f0;
                O[mf][j][2] *= f1; O[mf][j][3] *= f1;
            }
        }

        #pragma unroll
        for (int kc = 0; kc < 4; kc++) {
            uint32_t A[2][4];
            #pragma unroll
            for (int mf = 0; mf < 2; mf++) {
                float x0 = __shfl_sync(0xffffffffu, S[mf][kc][0], srcA);
                float x1 = __shfl_sync(0xffffffffu, S[mf][kc][1], srcA);
                float y0 = __shfl_sync(0xffffffffu, S[mf][kc][2], srcA);
                float y1 = __shfl_sync(0xffffffffu, S[mf][kc][3], srcA);
                float z0 = __shfl_sync(0xffffffffu, S[mf][kc][0], srcB);
                float z1 = __shfl_sync(0xffffffffu, S[mf][kc][1], srcB);
                float w0 = __shfl_sync(0xffffffffu, S[mf][kc][2], srcB);
                float w1 = __shfl_sync(0xffffffffu, S[mf][kc][3], srcB);
                A[mf][0] = __float_as_uint(odd ? x1 : x0);
                A[mf][1] = __float_as_uint(odd ? y1 : y0);
                A[mf][2] = __float_as_uint(odd ? z1 : z0);
                A[mf][3] = __float_as_uint(odd ? w1 : w0);
            }
            #pragma unroll
            for (int df = 0; df < 8; df++) {
                const float* vp = Vs + (kc * 8 + tig) * VSTR + df * 8 + gid;
                uint32_t b0 = __float_as_uint(vp[0]);
                uint32_t b1 = __float_as_uint(vp[4 * VSTR]);
                mma_tf32(O[0][df], A[0], b0, b1);
                mma_tf32(O[1][df], A[1], b0, b1);
            }
        }

        __syncthreads();
    }

    #pragma unroll
    for (int mf = 0; mf < 2; mf++) {
        const int rA = mf * 2, rB = mf * 2 + 1;
        const float inv0 = 1.f / lI[rA];
        const float inv1 = 1.f / lI[rB];
        float* Op0 = AO + ((size_t)b * Ss + (mf ? qrow1 : qrow0)) * 512 + h * 64;
        float* Op1 = Op0 + (size_t)8 * 512;
        #pragma unroll
        for (int df = 0; df < 8; df++) {
            float2 o0 = { O[mf][df][0] * inv0, O[mf][df][1] * inv0 };
            float2 o1 = { O[mf][df][2] * inv1, O[mf][df][3] * inv1 };
            *(float2*)(Op0 + df * 8 + 2 * tig) = o0;
            *(float2*)(Op1 + df * 8 + 2 * tig) = o1;
        }
    }
}

// ===========================================================================
// Residual + LayerNorm: 128 threads x float4 per 512-wide row.
// ===========================================================================
__global__ __launch_bounds__(128)
void ln_kernel(const float* __restrict__ q, const float* __restrict__ gamma,
               const float* __restrict__ beta, float* __restrict__ out) {
    __shared__ float rs[4], rs2[4];
    const int r = blockIdx.x;
    const int j = threadIdx.x;          // 0..127
    const int w = j >> 5, ln = j & 31;

    float4 qv = *(const float4*)(q + (size_t)r * 512 + j * 4);
    float4 pv = *(const float4*)(g_P + (size_t)r * 512 + j * 4);
    float4 v  = { qv.x + pv.x, qv.y + pv.y, qv.z + pv.z, qv.w + pv.w };

    float s  = v.x + v.y + v.z + v.w;
    float s2 = v.x * v.x + v.y * v.y + v.z * v.z + v.w * v.w;
    #pragma unroll
    for (int o = 16; o > 0; o >>= 1) {
        s  += __shfl_xor_sync(0xffffffffu, s,  o);
        s2 += __shfl_xor_sync(0xffffffffu, s2, o);
    }
    if (ln == 0) { rs[w] = s; rs2[w] = s2; }
    __syncthreads();
    s  = rs[0]  + rs[1]  + rs[2]  + rs[3];
    s2 = rs2[0] + rs2[1] + rs2[2] + rs2[3];

    const float mu  = s * (1.f / 512.f);
    const float var = s2 * (1.f / 512.f) - mu * mu;
    const float inv = rsqrtf(var + 1e-5f);

    float4 g4 = *(const float4*)(gamma + j * 4);
    float4 b4 = *(const float4*)(beta + j * 4);
    float4 o;
    o.x = (v.x - mu) * inv * g4.x + b4.x;
    o.y = (v.y - mu) * inv * g4.y + b4.y;
    o.z = (v.z - mu) * inv * g4.z + b4.z;
    o.w = (v.w - mu) * inv * g4.w + b4.w;
    *(float4*)(out + (size_t)r * 512 + j * 4) = o;
}

// ===========================================================================
extern "C" void kernel_launch(void* const* d_in, const int* in_sizes, int n_in,
                              void* d_out, int out_size) {
    const float* q     = (const float*)d_in[0];
    const float* k     = (const float*)d_in[1];
    const float* v     = (const float*)d_in[2];
    const float* mask  = (const float*)d_in[3];
    const float* Wq    = (const float*)d_in[4];
    const float* bq    = (const float*)d_in[5];
    const float* Wk    = (const float*)d_in[6];
    const float* bk    = (const float*)d_in[7];
    const float* Wv    = (const float*)d_in[8];
    const float* bv    = (const float*)d_in[9];
    const float* Wo    = (const float*)d_in[10];
    const float* bo    = (const float*)d_in[11];
    const float* gamma = (const float*)d_in[12];
    const float* beta  = (const float*)d_in[13];
    float* out = (float*)d_out;

    float *gQ, *gK, *gV, *gAO, *gP;
    cudaGetSymbolAddress((void**)&gQ,  g_Q);
    cudaGetSymbolAddress((void**)&gK,  g_K);
    cudaGetSymbolAddress((void**)&gV,  g_V);
    cudaGetSymbolAddress((void**)&gAO, g_AO);
    cudaGetSymbolAddress((void**)&gP,  g_P);

    dim3 gg(MROWS / 128, 512 / 128);
    gemm_tc_kernel<<<gg, 256>>>(q, Wq, bq, gQ);
    gemm_tc_kernel<<<gg, 256>>>(k, Wk, bk, gK);
    gemm_tc_kernel<<<gg, 256>>>(v, Wv, bv, gV);

    attn_mma_kernel<<<dim3(Ss / 128, Bb * Hh), 128>>>(gQ, gK, gV, mask, gAO);

    gemm_tc_kernel<<<gg, 256>>>(gAO, Wo, bo, gP);

    ln_kernel<<<MROWS, 128>>>(q, gamma, beta, out);
}

// round 11
// speedup vs baseline: 1.1204x; 1.1204x over previous
#include <cuda_runtime.h>
#include <cstddef>
#include <cstdint>

#define Bb   4
#define Ss   2048
#define DIN  512
#define Hh   8
#define DM   512
#define MROWS (Bb*Ss)          // 8192

// Scratch (device globals: allocation-free rule)
__device__ float g_Q [MROWS*DM];
__device__ float g_K [MROWS*DM];
__device__ float g_V [MROWS*DM];
__device__ float g_AO[MROWS*DM];
__device__ float g_P [MROWS*DIN];

// ===========================================================================
// helpers
// ===========================================================================
__device__ __forceinline__ uint32_t f2tf32(float f) {
    uint32_t r;
    asm("cvt.rna.tf32.f32 %0, %1;" : "=r"(r) : "f"(f));
    return r;
}

// D += A * B  (m16n8k8, tf32 inputs, fp32 accum). row.col.
__device__ __forceinline__ void mma_tf32(float* d, const uint32_t* a,
                                         uint32_t b0, uint32_t b1) {
    asm volatile(
        "mma.sync.aligned.m16n8k8.row.col.f32.tf32.tf32.f32 "
        "{%0,%1,%2,%3}, {%4,%5,%6,%7}, {%8,%9}, {%0,%1,%2,%3};"
        : "+f"(d[0]), "+f"(d[1]), "+f"(d[2]), "+f"(d[3])
        : "r"(a[0]), "r"(a[1]), "r"(a[2]), "r"(a[3]), "r"(b0), "r"(b1));
}

__device__ __forceinline__ void ldsm_x4(uint32_t* r, uint32_t addr) {
    asm volatile("ldmatrix.sync.aligned.m8n8.x4.shared.b16 {%0,%1,%2,%3}, [%4];"
                 : "=r"(r[0]), "=r"(r[1]), "=r"(r[2]), "=r"(r[3]) : "r"(addr));
}

// ===========================================================================
// Tensor-core GEMM (proven R5/R8 version, unchanged)
// ===========================================================================
#define XS_STR 36
#define WS_STR 136

__global__ __launch_bounds__(256)
void gemm_tc_kernel(const float* __restrict__ X, const float* __restrict__ W,
                    const float* __restrict__ bias, float* __restrict__ C) {
    __shared__ float Xs[128 * XS_STR];
    __shared__ float Ws[32 * WS_STR];

    const int tid  = threadIdx.x;
    const int lane = tid & 31;
    const int wid  = tid >> 5;
    const int gid  = lane >> 2;
    const int tig  = lane & 3;

    const int warp_m = wid >> 2;
    const int warp_n = wid & 3;
    const int m_base = warp_m * 64;
    const int n_base = warp_n * 32;

    const int bm = blockIdx.x * 128;
    const int bn = blockIdx.y * 128;

    float acc[4][4][4];
    #pragma unroll
    for (int mf = 0; mf < 4; mf++)
        #pragma unroll
        for (int nf = 0; nf < 4; nf++)
            #pragma unroll
            for (int c = 0; c < 4; c++) acc[mf][nf][c] = 0.f;

    for (int k0 = 0; k0 < 512; k0 += 32) {
        #pragma unroll
        for (int l = 0; l < 4; l++) {
            int e = tid + l * 256;
            int r = e >> 3, c4 = e & 7;
            float4 v = *(const float4*)(X + (size_t)(bm + r) * 512 + k0 + c4 * 4);
            uint4 t = { f2tf32(v.x), f2tf32(v.y), f2tf32(v.z), f2tf32(v.w) };
            *(uint4*)(Xs + r * XS_STR + c4 * 4) = t;
        }
        #pragma unroll
        for (int l = 0; l < 4; l++) {
            int e = tid + l * 256;
            int r = e >> 5, c4 = e & 31;
            float4 v = *(const float4*)(W + (size_t)(k0 + r) * 512 + bn + c4 * 4);
            uint4 t = { f2tf32(v.x), f2tf32(v.y), f2tf32(v.z), f2tf32(v.w) };
            *(uint4*)(Ws + r * WS_STR + c4 * 4) = t;
        }
        __syncthreads();

        #pragma unroll
        for (int ks = 0; ks < 4; ks++) {
            const int kk = ks * 8;
            uint32_t A[4][4];
            #pragma unroll
            for (int mf = 0; mf < 4; mf++) {
                const float* ap = Xs + (m_base + mf * 16 + gid) * XS_STR + kk + tig;
                A[mf][0] = __float_as_uint(ap[0]);
                A[mf][1] = __float_as_uint(ap[8 * XS_STR]);
                A[mf][2] = __float_as_uint(ap[4]);
                A[mf][3] = __float_as_uint(ap[8 * XS_STR + 4]);
            }
            #pragma unroll
            for (int nf = 0; nf < 4; nf++) {
                const float* bp = Ws + (kk + tig) * WS_STR + n_base + nf * 8 + gid;
                uint32_t b0 = __float_as_uint(bp[0]);
                uint32_t b1 = __float_as_uint(bp[4 * WS_STR]);
                #pragma unroll
                for (int mf = 0; mf < 4; mf++)
                    mma_tf32(acc[mf][nf], A[mf], b0, b1);
            }
        }
        __syncthreads();
    }

    #pragma unroll
    for (int nf = 0; nf < 4; nf++) {
        const int col = bn + n_base + nf * 8 + 2 * tig;
        float2 b2 = *(const float2*)(bias + col);
        #pragma unroll
        for (int mf = 0; mf < 4; mf++) {
            const int row0 = bm + m_base + mf * 16 + gid;
            float2 o0 = { acc[mf][nf][0] + b2.x, acc[mf][nf][1] + b2.y };
            float2 o1 = { acc[mf][nf][2] + b2.x, acc[mf][nf][3] + b2.y };
            *(float2*)(C + (size_t)row0 * 512 + col) = o0;
            *(float2*)(C + (size_t)(row0 + 8) * 512 + col) = o1;
        }
    }
}

// ===========================================================================
// mma.sync tf32 flash attention, v4 (proven R8 version, unchanged).
// ===========================================================================
#define KSTR 68
#define VSTR 72
#define SM_K0 0
#define SM_K1 (32*KSTR)
#define SM_V0 (2*32*KSTR)
#define SM_V1 (SM_V0 + 32*VSTR)
#define ATTN_SMEM_FLOATS (SM_V0 + 2*32*VSTR)   // 8960 floats = 35840 B

__global__ __launch_bounds__(128, 2)
void attn_mma_kernel(const float* __restrict__ Qg, const float* __restrict__ Kg,
                     const float* __restrict__ Vg, const float* __restrict__ mask,
                     float* __restrict__ AO) {
    __shared__ float sm[ATTN_SMEM_FLOATS];
    const int tid  = threadIdx.x;
    const int lane = tid & 31;
    const int wid  = tid >> 5;        // 0..3
    const int gid  = lane >> 2;
    const int tig  = lane & 3;
    const int srcA = (lane & ~3) | (tig >> 1);
    const int srcB = srcA + 2;
    const bool odd = (tig & 1);

    const int lm_base = (lane & 7) * KSTR + ((lane >> 3) & 1) * 4 + (lane >> 4) * 8;
    const uint32_t smK0_u = (uint32_t)__cvta_generic_to_shared(sm + SM_K0);
    const uint32_t smK1_u = (uint32_t)__cvta_generic_to_shared(sm + SM_K1);

    const int bh = blockIdx.y;
    const int b  = bh >> 3;
    const int h  = bh & 7;
    const int q0 = blockIdx.x * 128;

    const float* Kb = Kg + (size_t)b * Ss * 512 + h * 64;
    const float* Vb = Vg + (size_t)b * Ss * 512 + h * 64;

    const int qrow0 = q0 + wid * 32 + gid;
    const int qrow1 = qrow0 + 16;
    uint32_t Qa[2][8][4];
    #pragma unroll
    for (int mf = 0; mf < 2; mf++) {
        const float* Qp = Qg + ((size_t)b * Ss + (mf ? qrow1 : qrow0)) * 512 + h * 64;
        #pragma unroll
        for (int ch = 0; ch < 8; ch++) {
            Qa[mf][ch][0] = f2tf32(Qp[ch * 8 + tig] * 0.125f);
            Qa[mf][ch][1] = f2tf32(Qp[8 * 512 + ch * 8 + tig] * 0.125f);
            Qa[mf][ch][2] = f2tf32(Qp[ch * 8 + tig + 4] * 0.125f);
            Qa[mf][ch][3] = f2tf32(Qp[8 * 512 + ch * 8 + tig + 4] * 0.125f);
        }
    }

    auto load_kv = [&](int k0, int sel) {
        float* Ks = sm + (sel ? SM_K1 : SM_K0);
        float* Vs = sm + (sel ? SM_V1 : SM_V0);
        #pragma unroll
        for (int l = 0; l < 4; l++) {
            int e = tid + l * 128;
            int r = e >> 4, c4 = e & 15;
            float4 kv = *(const float4*)(Kb + (size_t)(k0 + r) * 512 + c4 * 4);
            uint4 tk = { f2tf32(kv.x), f2tf32(kv.y), f2tf32(kv.z), f2tf32(kv.w) };
            *(uint4*)(Ks + r * KSTR + c4 * 4) = tk;
            float4 vv = *(const float4*)(Vb + (size_t)(k0 + r) * 512 + c4 * 4);
            uint4 tv = { f2tf32(vv.x), f2tf32(vv.y), f2tf32(vv.z), f2tf32(vv.w) };
            *(uint4*)(Vs + r * VSTR + c4 * 4) = tv;
        }
    };

    load_kv(0, 0);

    const float* Mr[4];
    Mr[0] = mask + (size_t)b * Ss * Ss + (size_t)qrow0 * Ss;
    Mr[1] = Mr[0] + (size_t)8 * Ss;
    Mr[2] = mask + (size_t)b * Ss * Ss + (size_t)qrow1 * Ss;
    Mr[3] = Mr[2] + (size_t)8 * Ss;

    float mI[4] = {-1e30f, -1e30f, -1e30f, -1e30f};
    float lI[4] = {0.f, 0.f, 0.f, 0.f};
    float O[2][8][4];
    #pragma unroll
    for (int mf = 0; mf < 2; mf++)
        #pragma unroll
        for (int j = 0; j < 8; j++)
            #pragma unroll
            for (int c = 0; c < 4; c++) O[mf][j][c] = 0.f;

    __syncthreads();

    for (int kt = 0; kt < 64; kt++) {
        const int sel = kt & 1;
        const int k0  = kt * 32;
        const float* Vs = sm + (sel ? SM_V1 : SM_V0);
        const uint32_t smK_u = sel ? smK1_u : smK0_u;

        float2 mk[4][4];
        #pragma unroll
        for (int r = 0; r < 4; r++)
            #pragma unroll
            for (int kf = 0; kf < 4; kf++)
                mk[r][kf] = *(const float2*)(Mr[r] + k0 + kf * 8 + 2 * tig);

        float S[2][4][4];
        #pragma unroll
        for (int mf = 0; mf < 2; mf++)
            #pragma unroll
            for (int kf = 0; kf < 4; kf++)
                #pragma unroll
                for (int c = 0; c < 4; c++) S[mf][kf][c] = 0.f;

        #pragma unroll
        for (int kf = 0; kf < 4; kf++) {
            #pragma unroll
            for (int ch2 = 0; ch2 < 4; ch2++) {
                uint32_t r[4];
                ldsm_x4(r, smK_u + 4u * (uint32_t)(kf * 8 * KSTR + ch2 * 16 + lm_base));
                mma_tf32(S[0][kf], Qa[0][2 * ch2],     r[0], r[1]);
                mma_tf32(S[0][kf], Qa[0][2 * ch2 + 1], r[2], r[3]);
                mma_tf32(S[1][kf], Qa[1][2 * ch2],     r[0], r[1]);
                mma_tf32(S[1][kf], Qa[1][2 * ch2 + 1], r[2], r[3]);
            }
        }

        if (kt < 63) load_kv(k0 + 32, sel ^ 1);

        #pragma unroll
        for (int mf = 0; mf < 2; mf++) {
            const int rA = mf * 2, rB = mf * 2 + 1;
            float mx0 = mI[rA], mx1 = mI[rB];
            #pragma unroll
            for (int kf = 0; kf < 4; kf++) {
                float s0 = S[mf][kf][0] * mk[rA][kf].x;
                float s1 = S[mf][kf][1] * mk[rA][kf].y;
                float s2 = S[mf][kf][2] * mk[rB][kf].x;
                float s3 = S[mf][kf][3] * mk[rB][kf].y;
                s0 = (s0 > 0.f) ? s0 : -10000.f;
                s1 = (s1 > 0.f) ? s1 : -10000.f;
                s2 = (s2 > 0.f) ? s2 : -10000.f;
                s3 = (s3 > 0.f) ? s3 : -10000.f;
                S[mf][kf][0] = s0; S[mf][kf][1] = s1;
                S[mf][kf][2] = s2; S[mf][kf][3] = s3;
                mx0 = fmaxf(mx0, fmaxf(s0, s1));
                mx1 = fmaxf(mx1, fmaxf(s2, s3));
            }
            mx0 = fmaxf(mx0, __shfl_xor_sync(0xffffffffu, mx0, 1));
            mx0 = fmaxf(mx0, __shfl_xor_sync(0xffffffffu, mx0, 2));
            mx1 = fmaxf(mx1, __shfl_xor_sync(0xffffffffu, mx1, 1));
            mx1 = fmaxf(mx1, __shfl_xor_sync(0xffffffffu, mx1, 2));

            float f0 = __expf(mI[rA] - mx0);
            float f1 = __expf(mI[rB] - mx1);
            float sum0 = 0.f, sum1 = 0.f;
            #pragma unroll
            for (int kf = 0; kf < 4; kf++) {
                float p0 = __expf(S[mf][kf][0] - mx0);
                float p1 = __expf(S[mf][kf][1] - mx0);
                float p2 = __expf(S[mf][kf][2] - mx1);
                float p3 = __expf(S[mf][kf][3] - mx1);
                sum0 += p0 + p1;
                sum1 += p2 + p3;
                S[mf][kf][0] = __uint_as_float(f2tf32(p0));
                S[mf][kf][1] = __uint_as_float(f2tf32(p1));
                S[mf][kf][2] = __uint_as_float(f2tf32(p2));
                S[mf][kf][3] = __uint_as_float(f2tf32(p3));
            }
            sum0 += __shfl_xor_sync(0xffffffffu, sum0, 1);
            sum0 += __shfl_xor_sync(0xffffffffu, sum0, 2);
            sum1 += __shfl_xor_sync(0xffffffffu, sum1, 1);
            sum1 += __shfl_xor_sync(0xffffffffu, sum1, 2);

            lI[rA] = lI[rA] * f0 + sum0;  mI[rA] = mx0;
            lI[rB] = lI[rB] * f1 + sum1;  mI[rB] = mx1;

            #pragma unroll
            for (int j = 0; j < 8; j++) {
                O[mf][j][0] *= f0; O[mf][j][1] *= f0;
                O[mf][j][2] *= f1; O[mf][j][3] *= f1;
            }
        }

        #pragma unroll
        for (int kc = 0; kc < 4; kc++) {
            uint32_t A[2][4];
            #pragma unroll
            for (int mf = 0; mf < 2; mf++) {
                float x0 = __shfl_sync(0xffffffffu, S[mf][kc][0], srcA);
                float x1 = __shfl_sync(0xffffffffu, S[mf][kc][1], srcA);
                float y0 = __shfl_sync(0xffffffffu, S[mf][kc][2], srcA);
                float y1 = __shfl_sync(0xffffffffu, S[mf][kc][3], srcA);
                float z0 = __shfl_sync(0xffffffffu, S[mf][kc][0], srcB);
                float z1 = __shfl_sync(0xffffffffu, S[mf][kc][1], srcB);
                float w0 = __shfl_sync(0xffffffffu, S[mf][kc][2], srcB);
                float w1 = __shfl_sync(0xffffffffu, S[mf][kc][3], srcB);
                A[mf][0] = __float_as_uint(odd ? x1 : x0);
                A[mf][1] = __float_as_uint(odd ? y1 : y0);
                A[mf][2] = __float_as_uint(odd ? z1 : z0);
                A[mf][3] = __float_as_uint(odd ? w1 : w0);
            }
            #pragma unroll
            for (int df = 0; df < 8; df++) {
                const float* vp = Vs + (kc * 8 + tig) * VSTR + df * 8 + gid;
                uint32_t b0 = __float_as_uint(vp[0]);
                uint32_t b1 = __float_as_uint(vp[4 * VSTR]);
                mma_tf32(O[0][df], A[0], b0, b1);
                mma_tf32(O[1][df], A[1], b0, b1);
            }
        }

        __syncthreads();
    }

    #pragma unroll
    for (int mf = 0; mf < 2; mf++) {
        const int rA = mf * 2, rB = mf * 2 + 1;
        const float inv0 = 1.f / lI[rA];
        const float inv1 = 1.f / lI[rB];
        float* Op0 = AO + ((size_t)b * Ss + (mf ? qrow1 : qrow0)) * 512 + h * 64;
        float* Op1 = Op0 + (size_t)8 * 512;
        #pragma unroll
        for (int df = 0; df < 8; df++) {
            float2 o0 = { O[mf][df][0] * inv0, O[mf][df][1] * inv0 };
            float2 o1 = { O[mf][df][2] * inv1, O[mf][df][3] * inv1 };
            *(float2*)(Op0 + df * 8 + 2 * tig) = o0;
            *(float2*)(Op1 + df * 8 + 2 * tig) = o1;
        }
    }
}

// ===========================================================================
// Residual + LayerNorm: 128 threads x float4 per 512-wide row (proven R10).
// ===========================================================================
__global__ __launch_bounds__(128)
void ln_kernel(const float* __restrict__ q, const float* __restrict__ gamma,
               const float* __restrict__ beta, float* __restrict__ out) {
    __shared__ float rs[4], rs2[4];
    const int r = blockIdx.x;
    const int j = threadIdx.x;          // 0..127
    const int w = j >> 5, ln = j & 31;

    float4 qv = *(const float4*)(q + (size_t)r * 512 + j * 4);
    float4 pv = *(const float4*)(g_P + (size_t)r * 512 + j * 4);
    float4 v  = { qv.x + pv.x, qv.y + pv.y, qv.z + pv.z, qv.w + pv.w };

    float s  = v.x + v.y + v.z + v.w;
    float s2 = v.x * v.x + v.y * v.y + v.z * v.z + v.w * v.w;
    #pragma unroll
    for (int o = 16; o > 0; o >>= 1) {
        s  += __shfl_xor_sync(0xffffffffu, s,  o);
        s2 += __shfl_xor_sync(0xffffffffu, s2, o);
    }
    if (ln == 0) { rs[w] = s; rs2[w] = s2; }
    __syncthreads();
    s  = rs[0]  + rs[1]  + rs[2]  + rs[3];
    s2 = rs2[0] + rs2[1] + rs2[2] + rs2[3];

    const float mu  = s * (1.f / 512.f);
    const float var = s2 * (1.f / 512.f) - mu * mu;
    const float inv = rsqrtf(var + 1e-5f);

    float4 g4 = *(const float4*)(gamma + j * 4);
    float4 b4 = *(const float4*)(beta + j * 4);
    float4 o;
    o.x = (v.x - mu) * inv * g4.x + b4.x;
    o.y = (v.y - mu) * inv * g4.y + b4.y;
    o.z = (v.z - mu) * inv * g4.z + b4.z;
    o.w = (v.w - mu) * inv * g4.w + b4.w;
    *(float4*)(out + (size_t)r * 512 + j * 4) = o;
}

// ===========================================================================
extern "C" void kernel_launch(void* const* d_in, const int* in_sizes, int n_in,
                              void* d_out, int out_size) {
    const float* q     = (const float*)d_in[0];
    const float* k     = (const float*)d_in[1];
    const float* v     = (const float*)d_in[2];
    const float* mask  = (const float*)d_in[3];
    const float* Wq    = (const float*)d_in[4];
    const float* bq    = (const float*)d_in[5];
    const float* Wk    = (const float*)d_in[6];
    const float* bk    = (const float*)d_in[7];
    const float* Wv    = (const float*)d_in[8];
    const float* bv    = (const float*)d_in[9];
    const float* Wo    = (const float*)d_in[10];
    const float* bo    = (const float*)d_in[11];
    const float* gamma = (const float*)d_in[12];
    const float* beta  = (const float*)d_in[13];
    float* out = (float*)d_out;

    float *gQ, *gK, *gV, *gAO, *gP;
    cudaGetSymbolAddress((void**)&gQ,  g_Q);
    cudaGetSymbolAddress((void**)&gK,  g_K);
    cudaGetSymbolAddress((void**)&gV,  g_V);
    cudaGetSymbolAddress((void**)&gAO, g_AO);
    cudaGetSymbolAddress((void**)&gP,  g_P);

    dim3 gg(MROWS / 128, 512 / 128);
    gemm_tc_kernel<<<gg, 256>>>(q, Wq, bq, gQ);
    gemm_tc_kernel<<<gg, 256>>>(k, Wk, bk, gK);
    gemm_tc_kernel<<<gg, 256>>>(v, Wv, bv, gV);

    attn_mma_kernel<<<dim3(Ss / 128, Bb * Hh), 128>>>(gQ, gK, gV, mask, gAO);

    gemm_tc_kernel<<<gg, 256>>>(gAO, Wo, bo, gP);

    ln_kernel<<<MROWS, 128>>>(q, gamma, beta, out);
}